// round 4
// baseline (speedup 1.0000x reference)
#include <cuda_runtime.h>

#define CD    1024
#define NTOK  2048
#define BB    8
#define SCALE 0.0625f      // Dh^-0.5 = 1/16

// Scratch (static device globals; allocation-free)
__device__ float g_q0p[32 * 1024];         // q0 partials [cchunk][j]
__device__ float g_wk[4 * 1024];           // per-head score vectors (scaled)
__device__ float g_party[256 * 4 * 1024];  // flash partial y [blk][h][c]
__device__ float g_partm[256 * 4];         // flash partial max
__device__ float g_partz[256 * 4];         // flash partial Z
__device__ float g_ybar[8 * 4 * 1024];     // normalized att-weighted x rows
__device__ float g_p1[16 * 8 * 1024];      // gemv1 partials [cchunk][b][j]
__device__ float g_p2[16 * 8 * 1024];      // gemv2 partials [ichunk][b][j]

// ---------------------------------------------------------------------------
// K_A: q0 partials. q0[j] = sum_c tmp[c] * Wqkv[c][j]  (Q columns only)
// grid 32 (c-chunks of 32), 256 threads
__global__ void k_q0_part(const float* __restrict__ tmp,
                          const float* __restrict__ Wqkv) {
    int cc  = blockIdx.x;
    int tid = threadIdx.x;
    float acc0 = 0.f, acc1 = 0.f, acc2 = 0.f, acc3 = 0.f;
    #pragma unroll 4
    for (int r = 0; r < 32; ++r) {
        int c = cc * 32 + r;
        float tv = tmp[c];
        const float* row = Wqkv + (size_t)c * 3072;
        acc0 += tv * row[0 * 256 + tid];
        acc1 += tv * row[1 * 256 + tid];
        acc2 += tv * row[2 * 256 + tid];
        acc3 += tv * row[3 * 256 + tid];
    }
    g_q0p[cc * 1024 + 0 * 256 + tid] = acc0;
    g_q0p[cc * 1024 + 1 * 256 + tid] = acc1;
    g_q0p[cc * 1024 + 2 * 256 + tid] = acc2;
    g_q0p[cc * 1024 + 3 * 256 + tid] = acc3;
}

// ---------------------------------------------------------------------------
// K_B: reduce q0(+bias) in smem, then wk_h[c] = SCALE * sum_d Wk[c][h*256+d]*q0[h*256+d]
// grid 64 (16 c-rows per block, 2 per warp), 256 threads
__global__ void k_wk(const float* __restrict__ Wqkv,
                     const float* __restrict__ bqkv) {
    __shared__ float q0_s[1024];
    int tid = threadIdx.x;
    #pragma unroll
    for (int jj = 0; jj < 4; ++jj) {
        int j = jj * 256 + tid;
        float v = bqkv[j];
        #pragma unroll
        for (int cc = 0; cc < 32; ++cc) v += g_q0p[cc * 1024 + j];
        q0_s[j] = v;
    }
    __syncthreads();
    int warp = tid >> 5, lane = tid & 31;
    #pragma unroll
    for (int rr = 0; rr < 2; ++rr) {
        int c = blockIdx.x * 16 + warp * 2 + rr;
        const float* wrow = Wqkv + (size_t)c * 3072 + 1024;
        float acc[4] = {0.f, 0.f, 0.f, 0.f};
        #pragma unroll
        for (int q = 0; q < 32; ++q) {
            int j = q * 32 + lane;
            acc[q >> 3] += wrow[j] * q0_s[j];
        }
        #pragma unroll
        for (int h = 0; h < 4; ++h) {
            float v = acc[h];
            v += __shfl_xor_sync(0xffffffffu, v, 1);
            v += __shfl_xor_sync(0xffffffffu, v, 2);
            v += __shfl_xor_sync(0xffffffffu, v, 4);
            v += __shfl_xor_sync(0xffffffffu, v, 8);
            v += __shfl_xor_sync(0xffffffffu, v, 16);
            if (lane == 0) g_wk[h * 1024 + c] = v * SCALE;
        }
    }
}

// ---------------------------------------------------------------------------
// K_C: flash pass. Block = (batch, 64-token chunk); grid (32, 8).
// Thread t: head h=t&3, c-slice cs=t>>2 (16 floats). 2 groups of 32 tokens;
// scores-first: Phase A (32 dots, reg-staged from global), one reduce+softmax,
// Phase C re-reads the hot window from L1/L2. 3 barriers per 32 tokens.
__global__ __launch_bounds__(256, 2) void k_flash(const float* __restrict__ x) {
    __shared__ float ps[8][32][4];   // [warp][token][head] partial scores
    __shared__ float ss[32][4];      // reduced scores
    __shared__ float wws[32][4];     // exp weights
    __shared__ float fct[4];         // per-head rescale

    int tid   = threadIdx.x;
    int b     = blockIdx.y, chunk = blockIdx.x;
    int h     = tid & 3, cs = tid >> 2;
    int warp  = tid >> 5, lane = tid & 31;

    float wkr[16];
    #pragma unroll
    for (int k = 0; k < 16; ++k) wkr[k] = g_wk[h * 1024 + cs * 16 + k];
    float y[16];
    #pragma unroll
    for (int k = 0; k < 16; ++k) y[k] = 0.f;
    float m = -1e30f, Z = 0.f;   // managers (tid<4) only

    for (int g = 0; g < 2; ++g) {
        const float4* xb = (const float4*)(x
            + ((size_t)b * NTOK + (size_t)chunk * 64 + (size_t)g * 32) * CD);

        // Phase A: scores for 32 tokens over my 16-float slice
        float p[32];
        #pragma unroll
        for (int tt = 0; tt < 32; ++tt) {
            const float4* xr = xb + tt * 256 + cs * 4;
            float4 a0 = xr[0], a1 = xr[1], a2 = xr[2], a3 = xr[3];
            p[tt] = a0.x*wkr[0]  + a0.y*wkr[1]  + a0.z*wkr[2]  + a0.w*wkr[3]
                  + a1.x*wkr[4]  + a1.y*wkr[5]  + a1.z*wkr[6]  + a1.w*wkr[7]
                  + a2.x*wkr[8]  + a2.y*wkr[9]  + a2.z*wkr[10] + a2.w*wkr[11]
                  + a3.x*wkr[12] + a3.y*wkr[13] + a3.z*wkr[14] + a3.w*wkr[15];
        }
        #pragma unroll
        for (int tt = 0; tt < 32; ++tt) {
            p[tt] += __shfl_xor_sync(0xffffffffu, p[tt], 4);
            p[tt] += __shfl_xor_sync(0xffffffffu, p[tt], 8);
            p[tt] += __shfl_xor_sync(0xffffffffu, p[tt], 16);
        }
        if (lane < 4) {
            #pragma unroll
            for (int tt = 0; tt < 32; ++tt) ps[warp][tt][lane] = p[tt];
        }
        __syncthreads();                                   // (1)
        if (tid < 128) {                                   // (h2, tt) cover
            int h2 = tid & 3, tt = tid >> 2;
            float s = 0.f;
            #pragma unroll
            for (int w2 = 0; w2 < 8; ++w2) s += ps[w2][tt][h2];
            ss[tt][h2] = s;
        }
        __syncthreads();                                   // (2)
        if (tid < 4) {
            float mloc = m;
            #pragma unroll
            for (int tt = 0; tt < 32; ++tt) mloc = fmaxf(mloc, ss[tt][tid]);
            float f = __expf(m - mloc);
            float zadd = 0.f;
            #pragma unroll
            for (int tt = 0; tt < 32; ++tt) {
                float wv = __expf(ss[tt][tid] - mloc);
                wws[tt][tid] = wv;
                zadd += wv;
            }
            Z = Z * f + zadd;
            m = mloc;
            fct[tid] = f;
        }
        __syncthreads();                                   // (3)

        // Phase C: weighted accumulation (re-read from cache-hot window)
        float f = fct[h];
        #pragma unroll
        for (int k = 0; k < 16; ++k) y[k] *= f;
        #pragma unroll
        for (int tt = 0; tt < 32; ++tt) {
            float wv = wws[tt][h];
            const float4* xr = xb + tt * 256 + cs * 4;
            float4 a0 = xr[0], a1 = xr[1], a2 = xr[2], a3 = xr[3];
            y[0]  += wv * a0.x; y[1]  += wv * a0.y; y[2]  += wv * a0.z; y[3]  += wv * a0.w;
            y[4]  += wv * a1.x; y[5]  += wv * a1.y; y[6]  += wv * a1.z; y[7]  += wv * a1.w;
            y[8]  += wv * a2.x; y[9]  += wv * a2.y; y[10] += wv * a2.z; y[11] += wv * a2.w;
            y[12] += wv * a3.x; y[13] += wv * a3.y; y[14] += wv * a3.z; y[15] += wv * a3.w;
        }
        // barrier (1) of next group protects wws/fct reuse
    }

    int blk = b * 32 + chunk;
    float4* dst = (float4*)&g_party[((size_t)blk * 4 + h) * 1024 + cs * 16];
    dst[0] = make_float4(y[0],  y[1],  y[2],  y[3]);
    dst[1] = make_float4(y[4],  y[5],  y[6],  y[7]);
    dst[2] = make_float4(y[8],  y[9],  y[10], y[11]);
    dst[3] = make_float4(y[12], y[13], y[14], y[15]);
    if (tid < 4) {
        g_partm[blk * 4 + tid] = m;
        g_partz[blk * 4 + tid] = Z;
    }
}

// ---------------------------------------------------------------------------
// K_D: combine 32 chunk partials + class-token term -> ybar
// grid (4 heads, 8 batches), 256 threads
__global__ void k_combine(const float* __restrict__ tmp) {
    int h = blockIdx.x, b = blockIdx.y;
    int tid = threadIdx.x;
    __shared__ float red[8];
    __shared__ float s0_s;

    const float* wkh = g_wk + h * 1024;
    float pp = 0.f;
    #pragma unroll
    for (int k = 0; k < 4; ++k) pp += tmp[tid * 4 + k] * wkh[tid * 4 + k];
    pp += __shfl_xor_sync(0xffffffffu, pp, 1);
    pp += __shfl_xor_sync(0xffffffffu, pp, 2);
    pp += __shfl_xor_sync(0xffffffffu, pp, 4);
    pp += __shfl_xor_sync(0xffffffffu, pp, 8);
    pp += __shfl_xor_sync(0xffffffffu, pp, 16);
    int warp = tid >> 5, lane = tid & 31;
    if (lane == 0) red[warp] = pp;
    __syncthreads();
    if (tid == 0) {
        float s = 0.f;
        #pragma unroll
        for (int w = 0; w < 8; ++w) s += red[w];
        s0_s = s;
    }
    __syncthreads();
    float s0 = s0_s;

    float mv[32];
    float M = s0;
    #pragma unroll
    for (int i = 0; i < 32; ++i) {
        mv[i] = g_partm[(b * 32 + i) * 4 + h];
        M = fmaxf(M, mv[i]);
    }
    float e0 = __expf(s0 - M);
    float Zt = e0;
    float ef[32];
    #pragma unroll
    for (int i = 0; i < 32; ++i) {
        ef[i] = __expf(mv[i] - M);
        Zt += ef[i] * g_partz[(b * 32 + i) * 4 + h];
    }
    float inv = 1.f / Zt;

    float4 t4 = ((const float4*)tmp)[tid];
    float ax = e0 * t4.x, ay = e0 * t4.y, az = e0 * t4.z, aw = e0 * t4.w;
    #pragma unroll
    for (int i = 0; i < 32; ++i) {
        const float4* py = (const float4*)&g_party[((size_t)(b * 32 + i) * 4 + h) * 1024];
        float4 v = py[tid];
        ax += ef[i] * v.x; ay += ef[i] * v.y; az += ef[i] * v.z; aw += ef[i] * v.w;
    }
    ((float4*)&g_ybar[(size_t)(b * 4 + h) * 1024])[tid] =
        make_float4(ax * inv, ay * inv, az * inv, aw * inv);
}

// ---------------------------------------------------------------------------
// K_E: p1[cc][b][j] = sum_{c in chunk64} ybar[b][j>>8][c] * Wqkv[c][2048+j]
// grid (4 j-blocks==heads, 16 c-chunks of 64), 256 threads
__global__ void k_gemv1(const float* __restrict__ Wqkv) {
    int jblk = blockIdx.x;
    int cc   = blockIdx.y;
    int tid  = threadIdx.x;
    __shared__ float ys[8][64];
    for (int i = tid; i < 512; i += 256) {
        int bb = i >> 6, cr = i & 63;
        ys[bb][cr] = g_ybar[(size_t)(bb * 4 + jblk) * 1024 + cc * 64 + cr];
    }
    __syncthreads();
    int j = jblk * 256 + tid;
    float acc[8] = {0.f, 0.f, 0.f, 0.f, 0.f, 0.f, 0.f, 0.f};
    #pragma unroll 4
    for (int cr = 0; cr < 64; ++cr) {
        float w = Wqkv[(size_t)(cc * 64 + cr) * 3072 + 2048 + j];
        #pragma unroll
        for (int bb = 0; bb < 8; ++bb) acc[bb] += ys[bb][cr] * w;
    }
    #pragma unroll
    for (int bb = 0; bb < 8; ++bb)
        g_p1[(size_t)(cc * 8 + bb) * 1024 + j] = acc[bb];
}

// ---------------------------------------------------------------------------
// K_F: reduce p1 (+v bias) then p2[ic][b][j] = sum_{i in chunk64} out0[b][i]*Wv[i][j]
// grid (4 j-blocks, 16 i-chunks of 64), 256 threads
__global__ void k_gemv2(const float* __restrict__ Wv,
                        const float* __restrict__ bqkv) {
    int jblk = blockIdx.x;
    int ic   = blockIdx.y;
    int tid  = threadIdx.x;
    __shared__ float os[8][64];
    for (int idx = tid; idx < 512; idx += 256) {
        int bb = idx >> 6, ir = idx & 63;
        int i = ic * 64 + ir;
        float v = bqkv[2048 + i];
        #pragma unroll
        for (int cc = 0; cc < 16; ++cc) v += g_p1[(size_t)(cc * 8 + bb) * 1024 + i];
        os[bb][ir] = v;
    }
    __syncthreads();
    int j = jblk * 256 + tid;
    float acc[8] = {0.f, 0.f, 0.f, 0.f, 0.f, 0.f, 0.f, 0.f};
    #pragma unroll 4
    for (int ir = 0; ir < 64; ++ir) {
        float w = Wv[(size_t)(ic * 64 + ir) * 1024 + j];
        #pragma unroll
        for (int bb = 0; bb < 8; ++bb) acc[bb] += os[bb][ir] * w;
    }
    #pragma unroll
    for (int bb = 0; bb < 8; ++bb)
        g_p2[(size_t)(ic * 8 + bb) * 1024 + j] = acc[bb];
}

// ---------------------------------------------------------------------------
// K_G: reduce p2 + bv -> d_out [8,1024]
__global__ void k_final(const float* __restrict__ bv, float* __restrict__ out) {
    int idx = blockIdx.x * 256 + threadIdx.x;  // < 8192
    int bb = idx >> 10, j = idx & 1023;
    float v = bv[j];
    #pragma unroll
    for (int ic = 0; ic < 16; ++ic) v += g_p2[(size_t)(ic * 8 + bb) * 1024 + j];
    out[idx] = v;
}

// ---------------------------------------------------------------------------
extern "C" void kernel_launch(void* const* d_in, const int* in_sizes, int n_in,
                              void* d_out, int out_size) {
    const float* x    = (const float*)d_in[0];
    const float* tmp  = (const float*)d_in[1];
    const float* Wqkv = (const float*)d_in[2];
    const float* bqkv = (const float*)d_in[3];
    const float* Wv   = (const float*)d_in[4];
    const float* bv   = (const float*)d_in[5];

    k_q0_part<<<32, 256>>>(tmp, Wqkv);
    k_wk<<<64, 256>>>(Wqkv, bqkv);
    k_flash<<<dim3(32, 8), 256>>>(x);
    k_combine<<<dim3(4, 8), 256>>>(tmp);
    k_gemv1<<<dim3(4, 16), 256>>>(Wqkv);
    k_gemv2<<<dim3(4, 16), 256>>>(Wv, bqkv);
    k_final<<<32, 256>>>(bv, (float*)d_out);
}

// round 6
// speedup vs baseline: 2.0678x; 2.0678x over previous
#include <cuda_runtime.h>

#define CD    1024
#define NTOK  2048
#define BB    8
#define SCALE 0.0625f      // Dh^-0.5 = 1/16

// Scratch (static device globals; allocation-free)
__device__ float g_q0p[32 * 1024];           // q0 partials [cchunk][j]
__device__ float g_wk[4 * 1024];             // per-head score vectors (scaled)
__device__ float g_party[8 * 64 * 4 * 1024]; // flash partials [b][part][h][c]
__device__ float g_partm[8 * 64 * 4];        // flash partial max [b][part][h]
__device__ float g_partz[8 * 64 * 4];        // flash partial Z
__device__ float g_ybar[8 * 4 * 1024];       // normalized att-weighted x rows
__device__ float g_p1[16 * 8 * 1024];        // gemv1 partials [cchunk][b][j]
__device__ float g_p2[16 * 8 * 1024];        // gemv2 partials [ichunk][b][j]

// cp.async helpers
__device__ __forceinline__ void cp_async16(void* smem_dst, const void* gmem_src) {
    unsigned saddr = (unsigned)__cvta_generic_to_shared(smem_dst);
    asm volatile("cp.async.cg.shared.global [%0], [%1], 16;\n"
                 :: "r"(saddr), "l"(gmem_src) : "memory");
}
#define CP_COMMIT()  asm volatile("cp.async.commit_group;\n" ::: "memory")
#define CP_WAIT(n)   asm volatile("cp.async.wait_group %0;\n" :: "n"(n) : "memory")

// ---------------------------------------------------------------------------
// K_A: q0 partials. q0[j] = sum_c tmp[c] * Wqkv[c][j]  (Q columns only)
__global__ void k_q0_part(const float* __restrict__ tmp,
                          const float* __restrict__ Wqkv) {
    int cc  = blockIdx.x;
    int tid = threadIdx.x;
    float acc0 = 0.f, acc1 = 0.f, acc2 = 0.f, acc3 = 0.f;
    #pragma unroll 4
    for (int r = 0; r < 32; ++r) {
        int c = cc * 32 + r;
        float tv = tmp[c];
        const float* row = Wqkv + (size_t)c * 3072;
        acc0 += tv * row[0 * 256 + tid];
        acc1 += tv * row[1 * 256 + tid];
        acc2 += tv * row[2 * 256 + tid];
        acc3 += tv * row[3 * 256 + tid];
    }
    g_q0p[cc * 1024 + 0 * 256 + tid] = acc0;
    g_q0p[cc * 1024 + 1 * 256 + tid] = acc1;
    g_q0p[cc * 1024 + 2 * 256 + tid] = acc2;
    g_q0p[cc * 1024 + 3 * 256 + tid] = acc3;
}

// ---------------------------------------------------------------------------
// K_B: reduce q0(+bias) in smem, then wk_h[c] = SCALE * sum_d Wk[c][h*256+d]*q0[h*256+d]
__global__ void k_wk(const float* __restrict__ Wqkv,
                     const float* __restrict__ bqkv) {
    __shared__ float q0_s[1024];
    int tid = threadIdx.x;
    #pragma unroll
    for (int jj = 0; jj < 4; ++jj) {
        int j = jj * 256 + tid;
        float v = bqkv[j];
        #pragma unroll
        for (int cc = 0; cc < 32; ++cc) v += g_q0p[cc * 1024 + j];
        q0_s[j] = v;
    }
    __syncthreads();
    int warp = tid >> 5, lane = tid & 31;
    #pragma unroll
    for (int rr = 0; rr < 2; ++rr) {
        int c = blockIdx.x * 16 + warp * 2 + rr;
        const float* wrow = Wqkv + (size_t)c * 3072 + 1024;
        float acc[4] = {0.f, 0.f, 0.f, 0.f};
        #pragma unroll
        for (int q = 0; q < 32; ++q) {
            int j = q * 32 + lane;
            acc[q >> 3] += wrow[j] * q0_s[j];
        }
        #pragma unroll
        for (int h = 0; h < 4; ++h) {
            float v = acc[h];
            v += __shfl_xor_sync(0xffffffffu, v, 1);
            v += __shfl_xor_sync(0xffffffffu, v, 2);
            v += __shfl_xor_sync(0xffffffffu, v, 4);
            v += __shfl_xor_sync(0xffffffffu, v, 8);
            v += __shfl_xor_sync(0xffffffffu, v, 16);
            if (lane == 0) g_wk[h * 1024 + c] = v * SCALE;
        }
    }
}

// ---------------------------------------------------------------------------
// K_C: flash pass, warp-local online softmax.
// grid (32 chunks, 8 batches), 256 threads. Block = 64 tokens, 16 stages of 4
// tokens, cp.async double-buffered (2 x 16KB smem). Warp w: head = w&3,
// token-half = w>>2 (2 tokens/stage). Lane holds 32 channels of wk/y/x in regs.
__global__ __launch_bounds__(256, 2) void k_flash(const float* __restrict__ x) {
    __shared__ float4 buf[2][1024];   // [stage][4 tokens * 256 float4]

    int tid  = threadIdx.x;
    int warp = tid >> 5, lane = tid & 31;
    int h    = warp & 3, half = warp >> 2;
    int b    = blockIdx.y, chunk = blockIdx.x;

    float4 wk4[8], y4[8];
    const float4* wkp = (const float4*)g_wk + h * 256;
    #pragma unroll
    for (int k = 0; k < 8; ++k) {
        wk4[k] = wkp[lane + 32 * k];
        y4[k]  = make_float4(0.f, 0.f, 0.f, 0.f);
    }
    float m = -1e30f, Z = 0.f;

    const float4* xb = (const float4*)x + ((size_t)b * NTOK + (size_t)chunk * 64) * 256;

    // preload stage 0
    #pragma unroll
    for (int j = 0; j < 4; ++j)
        cp_async16(&buf[0][tid + 256 * j], xb + tid + 256 * j);
    CP_COMMIT();

    for (int s = 0; s < 16; ++s) {
        if (s + 1 < 16) {
            #pragma unroll
            for (int j = 0; j < 4; ++j)
                cp_async16(&buf[(s + 1) & 1][tid + 256 * j],
                           xb + (size_t)(s + 1) * 1024 + tid + 256 * j);
            CP_COMMIT();
            CP_WAIT(1);
        } else {
            CP_WAIT(0);
        }
        __syncthreads();

        const float4* base = &buf[s & 1][0];
        #pragma unroll
        for (int tt = 0; tt < 2; ++tt) {
            const float4* xr = base + (half * 2 + tt) * 256;
            float4 xv[8];
            float p = 0.f;
            #pragma unroll
            for (int k = 0; k < 8; ++k) {
                float4 a = xr[lane + 32 * k];
                xv[k] = a;
                p += a.x * wk4[k].x + a.y * wk4[k].y
                   + a.z * wk4[k].z + a.w * wk4[k].w;
            }
            p += __shfl_xor_sync(0xffffffffu, p, 1);
            p += __shfl_xor_sync(0xffffffffu, p, 2);
            p += __shfl_xor_sync(0xffffffffu, p, 4);
            p += __shfl_xor_sync(0xffffffffu, p, 8);
            p += __shfl_xor_sync(0xffffffffu, p, 16);

            float mn = fmaxf(m, p);
            float f  = __expf(m - mn);
            float wv = __expf(p - mn);
            Z = Z * f + wv;
            m = mn;
            #pragma unroll
            for (int k = 0; k < 8; ++k) {
                y4[k].x = y4[k].x * f + wv * xv[k].x;
                y4[k].y = y4[k].y * f + wv * xv[k].y;
                y4[k].z = y4[k].z * f + wv * xv[k].z;
                y4[k].w = y4[k].w * f + wv * xv[k].w;
            }
        }
        __syncthreads();   // protect buffer overwrite by next-next stage
    }

    int part = chunk * 2 + half;
    float4* dst = (float4*)&g_party[(((size_t)b * 64 + part) * 4 + h) * 1024];
    #pragma unroll
    for (int k = 0; k < 8; ++k) dst[lane + 32 * k] = y4[k];
    if (lane == 0) {
        g_partm[(b * 64 + part) * 4 + h] = m;
        g_partz[(b * 64 + part) * 4 + h] = Z;
    }
}

// ---------------------------------------------------------------------------
// K_D: combine 64 warp partials + class-token term -> ybar. No register arrays.
// grid (4 heads, 8 batches), 256 threads
__global__ void k_combine(const float* __restrict__ tmp) {
    int h = blockIdx.x, b = blockIdx.y;
    int tid = threadIdx.x;
    int warp = tid >> 5, lane = tid & 31;
    __shared__ float red[8];
    __shared__ float s0_s;
    __shared__ float sm[64], ez[64], coef[64];

    // s0 = tmp . wk_h
    const float* wkh = g_wk + h * 1024;
    float pp = 0.f;
    #pragma unroll
    for (int k = 0; k < 4; ++k) pp += tmp[tid * 4 + k] * wkh[tid * 4 + k];
    pp += __shfl_xor_sync(0xffffffffu, pp, 1);
    pp += __shfl_xor_sync(0xffffffffu, pp, 2);
    pp += __shfl_xor_sync(0xffffffffu, pp, 4);
    pp += __shfl_xor_sync(0xffffffffu, pp, 8);
    pp += __shfl_xor_sync(0xffffffffu, pp, 16);
    if (lane == 0) red[warp] = pp;
    if (tid < 64) {
        sm[tid] = g_partm[(b * 64 + tid) * 4 + h];
        ez[tid] = g_partz[(b * 64 + tid) * 4 + h];
    }
    __syncthreads();
    if (tid == 0) {
        float s = 0.f;
        #pragma unroll
        for (int w = 0; w < 8; ++w) s += red[w];
        s0_s = s;
    }
    __syncthreads();
    float s0 = s0_s;
    float M = s0;
    #pragma unroll 8
    for (int i = 0; i < 64; ++i) M = fmaxf(M, sm[i]);
    if (tid < 64) coef[tid] = __expf(sm[tid] - M);
    __syncthreads();
    float e0 = __expf(s0 - M);
    float Zt = e0;
    #pragma unroll 8
    for (int i = 0; i < 64; ++i) Zt += coef[i] * ez[i];
    float inv = 1.f / Zt;

    float4 t4 = ((const float4*)tmp)[tid];
    float ax = e0 * t4.x, ay = e0 * t4.y, az = e0 * t4.z, aw = e0 * t4.w;
    #pragma unroll 8
    for (int i = 0; i < 64; ++i) {
        float c = coef[i];
        const float4* py = (const float4*)&g_party[(((size_t)b * 64 + i) * 4 + h) * 1024];
        float4 v = py[tid];
        ax += c * v.x; ay += c * v.y; az += c * v.z; aw += c * v.w;
    }
    ((float4*)&g_ybar[(size_t)(b * 4 + h) * 1024])[tid] =
        make_float4(ax * inv, ay * inv, az * inv, aw * inv);
}

// ---------------------------------------------------------------------------
// K_E: p1[cc][b][j] = sum_{c in chunk64} ybar[b][j>>8][c] * Wqkv[c][2048+j]
__global__ void k_gemv1(const float* __restrict__ Wqkv) {
    int jblk = blockIdx.x;
    int cc   = blockIdx.y;
    int tid  = threadIdx.x;
    __shared__ float ys[8][64];
    for (int i = tid; i < 512; i += 256) {
        int bb = i >> 6, cr = i & 63;
        ys[bb][cr] = g_ybar[(size_t)(bb * 4 + jblk) * 1024 + cc * 64 + cr];
    }
    __syncthreads();
    int j = jblk * 256 + tid;
    float acc[8] = {0.f, 0.f, 0.f, 0.f, 0.f, 0.f, 0.f, 0.f};
    #pragma unroll 4
    for (int cr = 0; cr < 64; ++cr) {
        float w = Wqkv[(size_t)(cc * 64 + cr) * 3072 + 2048 + j];
        #pragma unroll
        for (int bb = 0; bb < 8; ++bb) acc[bb] += ys[bb][cr] * w;
    }
    #pragma unroll
    for (int bb = 0; bb < 8; ++bb)
        g_p1[(size_t)(cc * 8 + bb) * 1024 + j] = acc[bb];
}

// ---------------------------------------------------------------------------
// K_F: reduce p1 (+v bias) then p2[ic][b][j] = sum_{i in chunk64} out0[b][i]*Wv[i][j]
__global__ void k_gemv2(const float* __restrict__ Wv,
                        const float* __restrict__ bqkv) {
    int jblk = blockIdx.x;
    int ic   = blockIdx.y;
    int tid  = threadIdx.x;
    __shared__ float os[8][64];
    for (int idx = tid; idx < 512; idx += 256) {
        int bb = idx >> 6, ir = idx & 63;
        int i = ic * 64 + ir;
        float v = bqkv[2048 + i];
        #pragma unroll
        for (int cc = 0; cc < 16; ++cc) v += g_p1[(size_t)(cc * 8 + bb) * 1024 + i];
        os[bb][ir] = v;
    }
    __syncthreads();
    int j = jblk * 256 + tid;
    float acc[8] = {0.f, 0.f, 0.f, 0.f, 0.f, 0.f, 0.f, 0.f};
    #pragma unroll 4
    for (int ir = 0; ir < 64; ++ir) {
        float w = Wv[(size_t)(ic * 64 + ir) * 1024 + j];
        #pragma unroll
        for (int bb = 0; bb < 8; ++bb) acc[bb] += os[bb][ir] * w;
    }
    #pragma unroll
    for (int bb = 0; bb < 8; ++bb)
        g_p2[(size_t)(ic * 8 + bb) * 1024 + j] = acc[bb];
}

// ---------------------------------------------------------------------------
// K_G: reduce p2 + bv -> d_out [8,1024]
__global__ void k_final(const float* __restrict__ bv, float* __restrict__ out) {
    int idx = blockIdx.x * 256 + threadIdx.x;  // < 8192
    int bb = idx >> 10, j = idx & 1023;
    float v = bv[j];
    #pragma unroll
    for (int ic = 0; ic < 16; ++ic) v += g_p2[(size_t)(ic * 8 + bb) * 1024 + j];
    out[idx] = v;
}

// ---------------------------------------------------------------------------
extern "C" void kernel_launch(void* const* d_in, const int* in_sizes, int n_in,
                              void* d_out, int out_size) {
    const float* x    = (const float*)d_in[0];
    const float* tmp  = (const float*)d_in[1];
    const float* Wqkv = (const float*)d_in[2];
    const float* bqkv = (const float*)d_in[3];
    const float* Wv   = (const float*)d_in[4];
    const float* bv   = (const float*)d_in[5];

    k_q0_part<<<32, 256>>>(tmp, Wqkv);
    k_wk<<<64, 256>>>(Wqkv, bqkv);
    k_flash<<<dim3(32, 8), 256>>>(x);
    k_combine<<<dim3(4, 8), 256>>>(tmp);
    k_gemv1<<<dim3(4, 16), 256>>>(Wqkv);
    k_gemv2<<<dim3(4, 16), 256>>>(Wv, bqkv);
    k_final<<<32, 256>>>(bv, (float*)d_out);
}

// round 7
// speedup vs baseline: 2.7823x; 1.3455x over previous
#include <cuda_runtime.h>

#define CD    1024
#define NTOK  2048
#define BB    8
#define SCALE 0.0625f      // Dh^-0.5 = 1/16

// Scratch (static device globals; allocation-free)
__device__ float g_q0p[32 * 1024];           // q0 partials [cchunk][j]
__device__ float g_wk[4 * 1024];             // per-head score vectors (scaled)
__device__ float g_party[8 * 64 * 4 * 1024]; // flash partials [b][part][h][c]
__device__ float g_partm[8 * 64 * 4];        // flash partial max [b][part][h]
__device__ float g_partz[8 * 64 * 4];        // flash partial Z
__device__ float g_ybar[8 * 4 * 1024];       // normalized att-weighted x rows
__device__ float g_p1[16 * 8 * 1024];        // gemv1 partials [cchunk][b][j]
__device__ float g_p2[16 * 8 * 1024];        // gemv2 partials [ichunk][b][j]

// cp.async helpers
__device__ __forceinline__ void cp_async16(void* smem_dst, const void* gmem_src) {
    unsigned saddr = (unsigned)__cvta_generic_to_shared(smem_dst);
    asm volatile("cp.async.cg.shared.global [%0], [%1], 16;\n"
                 :: "r"(saddr), "l"(gmem_src) : "memory");
}
#define CP_COMMIT()  asm volatile("cp.async.commit_group;\n" ::: "memory")
#define CP_WAIT(n)   asm volatile("cp.async.wait_group %0;\n" :: "n"(n) : "memory")

// ---------------------------------------------------------------------------
// K_A: q0 partials. q0[j] = sum_c tmp[c] * Wqkv[c][j]  (Q columns only)
// grid 32 (c-chunks of 32), 256 threads. Manual 4-row batches (16 LDG each).
__global__ void k_q0_part(const float* __restrict__ tmp,
                          const float* __restrict__ Wqkv) {
    int cc  = blockIdx.x;
    int tid = threadIdx.x;
    float acc0 = 0.f, acc1 = 0.f, acc2 = 0.f, acc3 = 0.f;
    for (int r = 0; r < 32; r += 4) {
        int c = cc * 32 + r;
        float t0 = tmp[c], t1 = tmp[c + 1], t2 = tmp[c + 2], t3 = tmp[c + 3];
        const float* r0 = Wqkv + (size_t)c * 3072;
        const float* r1 = r0 + 3072;
        const float* r2 = r1 + 3072;
        const float* r3 = r2 + 3072;
        float a00 = r0[tid], a01 = r0[256 + tid], a02 = r0[512 + tid], a03 = r0[768 + tid];
        float a10 = r1[tid], a11 = r1[256 + tid], a12 = r1[512 + tid], a13 = r1[768 + tid];
        float a20 = r2[tid], a21 = r2[256 + tid], a22 = r2[512 + tid], a23 = r2[768 + tid];
        float a30 = r3[tid], a31 = r3[256 + tid], a32 = r3[512 + tid], a33 = r3[768 + tid];
        acc0 += t0 * a00 + t1 * a10 + t2 * a20 + t3 * a30;
        acc1 += t0 * a01 + t1 * a11 + t2 * a21 + t3 * a31;
        acc2 += t0 * a02 + t1 * a12 + t2 * a22 + t3 * a32;
        acc3 += t0 * a03 + t1 * a13 + t2 * a23 + t3 * a33;
    }
    g_q0p[cc * 1024 + 0 * 256 + tid] = acc0;
    g_q0p[cc * 1024 + 1 * 256 + tid] = acc1;
    g_q0p[cc * 1024 + 2 * 256 + tid] = acc2;
    g_q0p[cc * 1024 + 3 * 256 + tid] = acc3;
}

// ---------------------------------------------------------------------------
// K_B: reduce q0(+bias) in smem, then wk_h[c] = SCALE * sum_d Wk[c][h*256+d]*q0[h*256+d]
// grid 64 (16 c-rows per block, 2 per warp), 256 threads.
__global__ void k_wk(const float* __restrict__ Wqkv,
                     const float* __restrict__ bqkv) {
    __shared__ float q0_s[1024];
    int tid = threadIdx.x;
    #pragma unroll
    for (int jj = 0; jj < 4; ++jj) {
        int j = jj * 256 + tid;
        float s0 = 0.f, s1 = 0.f, s2 = 0.f, s3 = 0.f;
        for (int cc = 0; cc < 32; cc += 8) {
            float v0 = g_q0p[(cc + 0) * 1024 + j];
            float v1 = g_q0p[(cc + 1) * 1024 + j];
            float v2 = g_q0p[(cc + 2) * 1024 + j];
            float v3 = g_q0p[(cc + 3) * 1024 + j];
            float v4 = g_q0p[(cc + 4) * 1024 + j];
            float v5 = g_q0p[(cc + 5) * 1024 + j];
            float v6 = g_q0p[(cc + 6) * 1024 + j];
            float v7 = g_q0p[(cc + 7) * 1024 + j];
            s0 += v0 + v4; s1 += v1 + v5; s2 += v2 + v6; s3 += v3 + v7;
        }
        q0_s[j] = bqkv[j] + ((s0 + s1) + (s2 + s3));
    }
    __syncthreads();
    int warp = tid >> 5, lane = tid & 31;
    #pragma unroll
    for (int rr = 0; rr < 2; ++rr) {
        int c = blockIdx.x * 16 + warp * 2 + rr;
        const float* wrow = Wqkv + (size_t)c * 3072 + 1024;
        float acc[4] = {0.f, 0.f, 0.f, 0.f};
        #pragma unroll
        for (int q = 0; q < 32; ++q) {
            int j = q * 32 + lane;
            acc[q >> 3] += wrow[j] * q0_s[j];
        }
        #pragma unroll
        for (int h = 0; h < 4; ++h) {
            float v = acc[h];
            v += __shfl_xor_sync(0xffffffffu, v, 1);
            v += __shfl_xor_sync(0xffffffffu, v, 2);
            v += __shfl_xor_sync(0xffffffffu, v, 4);
            v += __shfl_xor_sync(0xffffffffu, v, 8);
            v += __shfl_xor_sync(0xffffffffu, v, 16);
            if (lane == 0) g_wk[h * 1024 + c] = v * SCALE;
        }
    }
}

// ---------------------------------------------------------------------------
// K_C: flash pass, warp-local online softmax, 4-deep cp.async ring.
// grid (32 chunks, 8 batches), 256 threads. Block = 64 tokens, 32 stages of
// 2 tokens (8 KB/stage, 32 KB ring). Warp w: head = w&3, token-half = w>>2.
// One barrier per stage; 3 stages always in flight.
__global__ __launch_bounds__(256, 2) void k_flash(const float* __restrict__ x) {
    __shared__ float4 buf[4][512];   // [slot][2 tokens * 256 float4]

    int tid  = threadIdx.x;
    int warp = tid >> 5, lane = tid & 31;
    int h    = warp & 3, half = warp >> 2;
    int b    = blockIdx.y, chunk = blockIdx.x;

    float4 wk4[8], y4[8];
    const float4* wkp = (const float4*)g_wk + h * 256;
    #pragma unroll
    for (int k = 0; k < 8; ++k) {
        wk4[k] = wkp[lane + 32 * k];
        y4[k]  = make_float4(0.f, 0.f, 0.f, 0.f);
    }
    float m = -1e30f, Z = 0.f;

    const float4* xb = (const float4*)x + ((size_t)b * NTOK + (size_t)chunk * 64) * 256;

    // preload stages 0..2
    #pragma unroll
    for (int s = 0; s < 3; ++s) {
        cp_async16(&buf[s][tid],       xb + (size_t)s * 512 + tid);
        cp_async16(&buf[s][tid + 256], xb + (size_t)s * 512 + 256 + tid);
        CP_COMMIT();
    }

    for (int s = 0; s < 32; ++s) {
        // drain so stage s is complete (tail-aware)
        if (s < 30)       { CP_WAIT(2); }
        else if (s == 30) { CP_WAIT(1); }
        else              { CP_WAIT(0); }
        __syncthreads();

        const float4* xr = &buf[s & 3][half * 256];
        // phase 1: dot
        float p = 0.f;
        #pragma unroll
        for (int k = 0; k < 8; ++k) {
            float4 a = xr[lane + 32 * k];
            p += a.x * wk4[k].x + a.y * wk4[k].y + a.z * wk4[k].z + a.w * wk4[k].w;
        }
        p += __shfl_xor_sync(0xffffffffu, p, 1);
        p += __shfl_xor_sync(0xffffffffu, p, 2);
        p += __shfl_xor_sync(0xffffffffu, p, 4);
        p += __shfl_xor_sync(0xffffffffu, p, 8);
        p += __shfl_xor_sync(0xffffffffu, p, 16);

        float mn = fmaxf(m, p);
        float f  = __expf(m - mn);
        float wv = __expf(p - mn);
        Z = Z * f + wv;
        m = mn;
        // phase 2: y update (re-read smem; keeps regs low)
        #pragma unroll
        for (int k = 0; k < 8; ++k) {
            float4 a = xr[lane + 32 * k];
            y4[k].x = y4[k].x * f + wv * a.x;
            y4[k].y = y4[k].y * f + wv * a.y;
            y4[k].z = y4[k].z * f + wv * a.z;
            y4[k].w = y4[k].w * f + wv * a.w;
        }

        // issue stage s+3 into slot of stage s-1 (safe: all threads passed
        // this stage's barrier, so s-1 is fully consumed)
        if (s + 3 < 32) {
            cp_async16(&buf[(s + 3) & 3][tid],       xb + (size_t)(s + 3) * 512 + tid);
            cp_async16(&buf[(s + 3) & 3][tid + 256], xb + (size_t)(s + 3) * 512 + 256 + tid);
            CP_COMMIT();
        }
    }

    int part = chunk * 2 + half;
    float4* dst = (float4*)&g_party[(((size_t)b * 64 + part) * 4 + h) * 1024];
    #pragma unroll
    for (int k = 0; k < 8; ++k) dst[lane + 32 * k] = y4[k];
    if (lane == 0) {
        g_partm[(b * 64 + part) * 4 + h] = m;
        g_partz[(b * 64 + part) * 4 + h] = Z;
    }
}

// ---------------------------------------------------------------------------
// K_D: combine 64 warp partials + class-token term -> ybar.
// grid (4 heads, 8 batches), 256 threads. Manual 8-wide load batches (MLP=8).
__global__ void k_combine(const float* __restrict__ tmp) {
    int h = blockIdx.x, b = blockIdx.y;
    int tid = threadIdx.x;
    int warp = tid >> 5, lane = tid & 31;
    __shared__ float red[8];
    __shared__ float s0_s;
    __shared__ float sm[64], ez[64], coef[64];

    // s0 = tmp . wk_h
    const float* wkh = g_wk + h * 1024;
    float pp = 0.f;
    #pragma unroll
    for (int k = 0; k < 4; ++k) pp += tmp[tid * 4 + k] * wkh[tid * 4 + k];
    pp += __shfl_xor_sync(0xffffffffu, pp, 1);
    pp += __shfl_xor_sync(0xffffffffu, pp, 2);
    pp += __shfl_xor_sync(0xffffffffu, pp, 4);
    pp += __shfl_xor_sync(0xffffffffu, pp, 8);
    pp += __shfl_xor_sync(0xffffffffu, pp, 16);
    if (lane == 0) red[warp] = pp;
    if (tid < 64) {
        sm[tid] = g_partm[(b * 64 + tid) * 4 + h];
        ez[tid] = g_partz[(b * 64 + tid) * 4 + h];
    }
    __syncthreads();
    if (tid == 0) {
        float s = 0.f;
        #pragma unroll
        for (int w = 0; w < 8; ++w) s += red[w];
        s0_s = s;
    }
    __syncthreads();
    float s0 = s0_s;
    float M = s0;
    #pragma unroll
    for (int i = 0; i < 64; ++i) M = fmaxf(M, sm[i]);
    if (tid < 64) coef[tid] = __expf(sm[tid] - M);
    __syncthreads();
    float e0 = __expf(s0 - M);
    float Zt = e0;
    #pragma unroll
    for (int i = 0; i < 64; ++i) Zt += coef[i] * ez[i];
    float inv = 1.f / Zt;

    const float* pybase = &g_party[(size_t)b * 64 * 4096 + (size_t)h * 1024];
    float4 t4 = ((const float4*)tmp)[tid];
    float ax = e0 * t4.x, ay = e0 * t4.y, az = e0 * t4.z, aw = e0 * t4.w;
    float bx = 0.f, by = 0.f, bz = 0.f, bw = 0.f;
    for (int i0 = 0; i0 < 64; i0 += 8) {
        // 8 explicit independent loads (16 KB apart) — forces MLP=8
        float4 v0 = ((const float4*)(pybase + (size_t)(i0 + 0) * 4096))[tid];
        float4 v1 = ((const float4*)(pybase + (size_t)(i0 + 1) * 4096))[tid];
        float4 v2 = ((const float4*)(pybase + (size_t)(i0 + 2) * 4096))[tid];
        float4 v3 = ((const float4*)(pybase + (size_t)(i0 + 3) * 4096))[tid];
        float4 v4 = ((const float4*)(pybase + (size_t)(i0 + 4) * 4096))[tid];
        float4 v5 = ((const float4*)(pybase + (size_t)(i0 + 5) * 4096))[tid];
        float4 v6 = ((const float4*)(pybase + (size_t)(i0 + 6) * 4096))[tid];
        float4 v7 = ((const float4*)(pybase + (size_t)(i0 + 7) * 4096))[tid];
        float c0 = coef[i0 + 0], c1 = coef[i0 + 1], c2 = coef[i0 + 2], c3 = coef[i0 + 3];
        float c4 = coef[i0 + 4], c5 = coef[i0 + 5], c6 = coef[i0 + 6], c7 = coef[i0 + 7];
        ax += c0 * v0.x + c2 * v2.x + c4 * v4.x + c6 * v6.x;
        ay += c0 * v0.y + c2 * v2.y + c4 * v4.y + c6 * v6.y;
        az += c0 * v0.z + c2 * v2.z + c4 * v4.z + c6 * v6.z;
        aw += c0 * v0.w + c2 * v2.w + c4 * v4.w + c6 * v6.w;
        bx += c1 * v1.x + c3 * v3.x + c5 * v5.x + c7 * v7.x;
        by += c1 * v1.y + c3 * v3.y + c5 * v5.y + c7 * v7.y;
        bz += c1 * v1.z + c3 * v3.z + c5 * v5.z + c7 * v7.z;
        bw += c1 * v1.w + c3 * v3.w + c5 * v5.w + c7 * v7.w;
    }
    ((float4*)&g_ybar[(size_t)(b * 4 + h) * 1024])[tid] =
        make_float4((ax + bx) * inv, (ay + by) * inv, (az + bz) * inv, (aw + bw) * inv);
}

// ---------------------------------------------------------------------------
// K_E: p1[cc][b][j] = sum_{c in chunk64} ybar[b][j>>8][c] * Wqkv[c][2048+j]
// grid (4 j-blocks==heads, 16 c-chunks of 64), 256 threads. 8-wide W batches.
__global__ void k_gemv1(const float* __restrict__ Wqkv) {
    int jblk = blockIdx.x;
    int cc   = blockIdx.y;
    int tid  = threadIdx.x;
    __shared__ float ys[8][64];
    for (int i = tid; i < 512; i += 256) {
        int bb = i >> 6, cr = i & 63;
        ys[bb][cr] = g_ybar[(size_t)(bb * 4 + jblk) * 1024 + cc * 64 + cr];
    }
    __syncthreads();
    int j = jblk * 256 + tid;
    const float* Wcol = Wqkv + 2048 + j;
    float acc[8] = {0.f, 0.f, 0.f, 0.f, 0.f, 0.f, 0.f, 0.f};
    for (int cr0 = 0; cr0 < 64; cr0 += 8) {
        size_t base = (size_t)(cc * 64 + cr0) * 3072;
        float w0 = Wcol[base + 0 * 3072];
        float w1 = Wcol[base + 1 * 3072];
        float w2 = Wcol[base + 2 * 3072];
        float w3 = Wcol[base + 3 * 3072];
        float w4 = Wcol[base + 4 * 3072];
        float w5 = Wcol[base + 5 * 3072];
        float w6 = Wcol[base + 6 * 3072];
        float w7 = Wcol[base + 7 * 3072];
        #pragma unroll
        for (int bb = 0; bb < 8; ++bb) {
            float t0 = ys[bb][cr0 + 0] * w0 + ys[bb][cr0 + 1] * w1
                     + ys[bb][cr0 + 2] * w2 + ys[bb][cr0 + 3] * w3;
            float t1 = ys[bb][cr0 + 4] * w4 + ys[bb][cr0 + 5] * w5
                     + ys[bb][cr0 + 6] * w6 + ys[bb][cr0 + 7] * w7;
            acc[bb] += t0 + t1;
        }
    }
    #pragma unroll
    for (int bb = 0; bb < 8; ++bb)
        g_p1[(size_t)(cc * 8 + bb) * 1024 + j] = acc[bb];
}

// ---------------------------------------------------------------------------
// K_F: reduce p1 (+v bias) then p2[ic][b][j] = sum_{i in chunk64} out0[b][i]*Wv[i][j]
// grid (4 j-blocks, 16 i-chunks of 64), 256 threads. 8-wide W batches.
__global__ void k_gemv2(const float* __restrict__ Wv,
                        const float* __restrict__ bqkv) {
    int jblk = blockIdx.x;
    int ic   = blockIdx.y;
    int tid  = threadIdx.x;
    __shared__ float os[8][64];
    for (int idx = tid; idx < 512; idx += 256) {
        int bb = idx >> 6, ir = idx & 63;
        int i = ic * 64 + ir;
        float s0 = 0.f, s1 = 0.f, s2 = 0.f, s3 = 0.f;
        #pragma unroll
        for (int cc = 0; cc < 16; cc += 4) {
            s0 += g_p1[(size_t)((cc + 0) * 8 + bb) * 1024 + i];
            s1 += g_p1[(size_t)((cc + 1) * 8 + bb) * 1024 + i];
            s2 += g_p1[(size_t)((cc + 2) * 8 + bb) * 1024 + i];
            s3 += g_p1[(size_t)((cc + 3) * 8 + bb) * 1024 + i];
        }
        os[bb][ir] = bqkv[2048 + i] + ((s0 + s1) + (s2 + s3));
    }
    __syncthreads();
    int j = jblk * 256 + tid;
    const float* Wcol = Wv + j;
    float acc[8] = {0.f, 0.f, 0.f, 0.f, 0.f, 0.f, 0.f, 0.f};
    for (int ir0 = 0; ir0 < 64; ir0 += 8) {
        size_t base = (size_t)(ic * 64 + ir0) * 1024;
        float w0 = Wcol[base + 0 * 1024];
        float w1 = Wcol[base + 1 * 1024];
        float w2 = Wcol[base + 2 * 1024];
        float w3 = Wcol[base + 3 * 1024];
        float w4 = Wcol[base + 4 * 1024];
        float w5 = Wcol[base + 5 * 1024];
        float w6 = Wcol[base + 6 * 1024];
        float w7 = Wcol[base + 7 * 1024];
        #pragma unroll
        for (int bb = 0; bb < 8; ++bb) {
            float t0 = os[bb][ir0 + 0] * w0 + os[bb][ir0 + 1] * w1
                     + os[bb][ir0 + 2] * w2 + os[bb][ir0 + 3] * w3;
            float t1 = os[bb][ir0 + 4] * w4 + os[bb][ir0 + 5] * w5
                     + os[bb][ir0 + 6] * w6 + os[bb][ir0 + 7] * w7;
            acc[bb] += t0 + t1;
        }
    }
    #pragma unroll
    for (int bb = 0; bb < 8; ++bb)
        g_p2[(size_t)(ic * 8 + bb) * 1024 + j] = acc[bb];
}

// ---------------------------------------------------------------------------
// K_G: reduce p2 + bv -> d_out [8,1024]
__global__ void k_final(const float* __restrict__ bv, float* __restrict__ out) {
    int idx = blockIdx.x * 256 + threadIdx.x;  // < 8192
    int bb = idx >> 10, j = idx & 1023;
    float s0 = 0.f, s1 = 0.f, s2 = 0.f, s3 = 0.f;
    #pragma unroll
    for (int ic = 0; ic < 16; ic += 4) {
        s0 += g_p2[(size_t)((ic + 0) * 8 + bb) * 1024 + j];
        s1 += g_p2[(size_t)((ic + 1) * 8 + bb) * 1024 + j];
        s2 += g_p2[(size_t)((ic + 2) * 8 + bb) * 1024 + j];
        s3 += g_p2[(size_t)((ic + 3) * 8 + bb) * 1024 + j];
    }
    out[idx] = bv[j] + ((s0 + s1) + (s2 + s3));
}

// ---------------------------------------------------------------------------
extern "C" void kernel_launch(void* const* d_in, const int* in_sizes, int n_in,
                              void* d_out, int out_size) {
    const float* x    = (const float*)d_in[0];
    const float* tmp  = (const float*)d_in[1];
    const float* Wqkv = (const float*)d_in[2];
    const float* bqkv = (const float*)d_in[3];
    const float* Wv   = (const float*)d_in[4];
    const float* bv   = (const float*)d_in[5];

    k_q0_part<<<32, 256>>>(tmp, Wqkv);
    k_wk<<<64, 256>>>(Wqkv, bqkv);
    k_flash<<<dim3(32, 8), 256>>>(x);
    k_combine<<<dim3(4, 8), 256>>>(tmp);
    k_gemv1<<<dim3(4, 16), 256>>>(Wqkv);
    k_gemv2<<<dim3(4, 16), 256>>>(Wv, bqkv);
    k_final<<<32, 256>>>(bv, (float*)d_out);
}

// round 9
// speedup vs baseline: 4.0776x; 1.4656x over previous
#include <cuda_runtime.h>

#define CD    1024
#define NTOK  2048
#define SCALE 0.0625f      // Dh^-0.5 = 1/16
#define GR    256          // grid size (must be <= 148*2 for co-residency)

// Scratch (static device globals; allocation-free)
__device__ float g_q0p[64 * 1024];            // q0 partials [cchunk64][j]
__device__ float g_q0[1024];                  // q0 final
__device__ float g_wk[4 * 1024];              // per-head score vectors (scaled)
__device__ float g_party[8 * 32 * 4 * 1024];  // flash partials [b][part32][h][c]  (4 MB)
__device__ float g_partm[8 * 32 * 4];
__device__ float g_partz[8 * 32 * 4];
__device__ float g_ybar[8 * 4 * 1024];
__device__ float g_out0[8 * 1024];
__device__ float g_p1[64 * 8 * 1024];         // [cc64][b][j] (2 MB)
__device__ float g_p2[64 * 8 * 1024];         // [ic64][b][j] (2 MB)
__device__ unsigned g_bar[16];                // global barrier counters (self-resetting)

// cp.async helpers
__device__ __forceinline__ void cp_async16(void* smem_dst, const void* gmem_src) {
    unsigned saddr = (unsigned)__cvta_generic_to_shared(smem_dst);
    asm volatile("cp.async.cg.shared.global [%0], [%1], 16;\n"
                 :: "r"(saddr), "l"(gmem_src) : "memory");
}
#define CP_COMMIT()  asm volatile("cp.async.commit_group;\n" ::: "memory")
#define CP_WAIT(n)   asm volatile("cp.async.wait_group %0;\n" :: "n"(n) : "memory")

// Global barrier: all GR blocks are co-resident (GR <= 296), so spin is safe.
__device__ __forceinline__ void gbar(int i) {
    __syncthreads();
    if (threadIdx.x == 0) {
        __threadfence();
        atomicAdd(&g_bar[i], 1u);
        volatile unsigned* p = &g_bar[i];
        while (*p < GR) { }
        __threadfence();
    }
    __syncthreads();
}

__global__ __launch_bounds__(256, 2)
void k_fused(const float* __restrict__ x,
             const float* __restrict__ tmp,
             const float* __restrict__ Wqkv,
             const float* __restrict__ bqkv,
             const float* __restrict__ Wv,
             const float* __restrict__ bv,
             float* __restrict__ out) {
    __shared__ __align__(16) char sraw[33024];
    int blk = blockIdx.x, tid = threadIdx.x;
    int warp = tid >> 5, lane = tid & 31;

    // ======================= Phase A: q0 partials =======================
    // blocks 0..63, 16 c-rows each; thread: 4 j-cols; 4-row batches (16 LDG)
    if (blk < 64) {
        float a0 = 0.f, a1 = 0.f, a2 = 0.f, a3 = 0.f;
        for (int r = 0; r < 16; r += 4) {
            int c = blk * 16 + r;
            float t0 = tmp[c], t1 = tmp[c + 1], t2 = tmp[c + 2], t3 = tmp[c + 3];
            const float* r0 = Wqkv + (size_t)c * 3072;
            const float* r1 = r0 + 3072;
            const float* r2 = r1 + 3072;
            const float* r3 = r2 + 3072;
            float v00 = r0[tid], v01 = r0[256 + tid], v02 = r0[512 + tid], v03 = r0[768 + tid];
            float v10 = r1[tid], v11 = r1[256 + tid], v12 = r1[512 + tid], v13 = r1[768 + tid];
            float v20 = r2[tid], v21 = r2[256 + tid], v22 = r2[512 + tid], v23 = r2[768 + tid];
            float v30 = r3[tid], v31 = r3[256 + tid], v32 = r3[512 + tid], v33 = r3[768 + tid];
            a0 += t0 * v00 + t1 * v10 + t2 * v20 + t3 * v30;
            a1 += t0 * v01 + t1 * v11 + t2 * v21 + t3 * v31;
            a2 += t0 * v02 + t1 * v12 + t2 * v22 + t3 * v32;
            a3 += t0 * v03 + t1 * v13 + t2 * v23 + t3 * v33;
        }
        g_q0p[blk * 1024 + 0 * 256 + tid] = a0;
        g_q0p[blk * 1024 + 1 * 256 + tid] = a1;
        g_q0p[blk * 1024 + 2 * 256 + tid] = a2;
        g_q0p[blk * 1024 + 3 * 256 + tid] = a3;
    }
    gbar(0);

    // ======================= Phase A2: q0 reduce =======================
    // blocks 0..3, 256 j each; 64 partials, 8-wide batches
    if (blk < 4) {
        int j = blk * 256 + tid;
        float s0 = 0.f, s1 = 0.f;
        for (int cc = 0; cc < 64; cc += 8) {
            float v0 = g_q0p[(cc + 0) * 1024 + j];
            float v1 = g_q0p[(cc + 1) * 1024 + j];
            float v2 = g_q0p[(cc + 2) * 1024 + j];
            float v3 = g_q0p[(cc + 3) * 1024 + j];
            float v4 = g_q0p[(cc + 4) * 1024 + j];
            float v5 = g_q0p[(cc + 5) * 1024 + j];
            float v6 = g_q0p[(cc + 6) * 1024 + j];
            float v7 = g_q0p[(cc + 7) * 1024 + j];
            s0 += (v0 + v1) + (v2 + v3);
            s1 += (v4 + v5) + (v6 + v7);
        }
        g_q0[j] = bqkv[j] + s0 + s1;
    }
    gbar(1);

    // ======================= Phase B: wk =======================
    // 256 blocks, 4 c-rows each; warp w: row w>>1, j-half w&1 (2 heads per warp)
    {
        float* qs = (float*)sraw;
        qs[tid] = g_q0[tid];
        qs[256 + tid] = g_q0[256 + tid];
        qs[512 + tid] = g_q0[512 + tid];
        qs[768 + tid] = g_q0[768 + tid];
        __syncthreads();
        int r = warp >> 1, halfj = warp & 1;
        int c = blk * 4 + r;
        const float* wrow = Wqkv + (size_t)c * 3072 + 1024 + halfj * 512;
        const float* qsh = qs + halfj * 512;
        float acc0 = 0.f, acc1 = 0.f;
        #pragma unroll
        for (int q = 0; q < 8; ++q) acc0 += wrow[q * 32 + lane] * qsh[q * 32 + lane];
        #pragma unroll
        for (int q = 8; q < 16; ++q) acc1 += wrow[q * 32 + lane] * qsh[q * 32 + lane];
        #pragma unroll
        for (int d = 1; d < 32; d <<= 1) {
            acc0 += __shfl_xor_sync(0xffffffffu, acc0, d);
            acc1 += __shfl_xor_sync(0xffffffffu, acc1, d);
        }
        if (lane == 0) {
            g_wk[(halfj * 2 + 0) * 1024 + c] = acc0 * SCALE;
            g_wk[(halfj * 2 + 1) * 1024 + c] = acc1 * SCALE;
        }
    }
    gbar(2);

    // ======================= Phase C: flash =======================
    // 256 blocks: b = blk>>5, chunk = blk&31 (64 tokens). 4-deep cp.async ring.
    {
        float4 (*ring)[512] = reinterpret_cast<float4(*)[512]>(sraw);
        int h = warp & 3, half = warp >> 2;
        int b = blk >> 5, chunk = blk & 31;

        float4 wk4[8], y4[8];
        const float4* wkp = (const float4*)g_wk + h * 256;
        #pragma unroll
        for (int k = 0; k < 8; ++k) {
            wk4[k] = wkp[lane + 32 * k];
            y4[k]  = make_float4(0.f, 0.f, 0.f, 0.f);
        }
        float m = -1e30f, Z = 0.f;

        const float4* xb = (const float4*)x + ((size_t)b * NTOK + (size_t)chunk * 64) * 256;

        #pragma unroll
        for (int s = 0; s < 3; ++s) {
            cp_async16(&ring[s][tid],       xb + (size_t)s * 512 + tid);
            cp_async16(&ring[s][tid + 256], xb + (size_t)s * 512 + 256 + tid);
            CP_COMMIT();
        }

        for (int s = 0; s < 32; ++s) {
            if (s < 30)       { CP_WAIT(2); }
            else if (s == 30) { CP_WAIT(1); }
            else              { CP_WAIT(0); }
            __syncthreads();

            const float4* xr = &ring[s & 3][half * 256];
            float p = 0.f;
            #pragma unroll
            for (int k = 0; k < 8; ++k) {
                float4 a = xr[lane + 32 * k];
                p += a.x * wk4[k].x + a.y * wk4[k].y + a.z * wk4[k].z + a.w * wk4[k].w;
            }
            #pragma unroll
            for (int d = 1; d < 32; d <<= 1) p += __shfl_xor_sync(0xffffffffu, p, d);

            float mn = fmaxf(m, p);
            float f  = __expf(m - mn);
            float wv = __expf(p - mn);
            Z = Z * f + wv;
            m = mn;
            #pragma unroll
            for (int k = 0; k < 8; ++k) {
                float4 a = xr[lane + 32 * k];
                y4[k].x = y4[k].x * f + wv * a.x;
                y4[k].y = y4[k].y * f + wv * a.y;
                y4[k].z = y4[k].z * f + wv * a.z;
                y4[k].w = y4[k].w * f + wv * a.w;
            }

            if (s + 3 < 32) {
                cp_async16(&ring[(s + 3) & 3][tid],       xb + (size_t)(s + 3) * 512 + tid);
                cp_async16(&ring[(s + 3) & 3][tid + 256], xb + (size_t)(s + 3) * 512 + 256 + tid);
                CP_COMMIT();
            }
        }

        // half-merge within block: warps (h, half=1) -> smem; (h, half=0) combine
        __syncthreads();
        float* mbuf = (float*)sraw;             // 4 heads x 1024 floats
        float* mz   = (float*)(sraw + 16384);   // 4 x {m, Z}
        if (half == 1) {
            float4* d4 = (float4*)(mbuf + h * 1024);
            #pragma unroll
            for (int k = 0; k < 8; ++k) d4[lane + 32 * k] = y4[k];
            if (lane == 0) { mz[h * 2] = m; mz[h * 2 + 1] = Z; }
        }
        __syncthreads();
        if (half == 0) {
            float m1 = mz[h * 2], Z1 = mz[h * 2 + 1];
            float mm = fmaxf(m, m1);
            float f0 = __expf(m - mm), f1 = __expf(m1 - mm);
            const float4* s4 = (const float4*)(mbuf + h * 1024);
            float4* dst = (float4*)&g_party[(((size_t)b * 32 + chunk) * 4 + h) * 1024];
            #pragma unroll
            for (int k = 0; k < 8; ++k) {
                float4 a = s4[lane + 32 * k];
                float4 o;
                o.x = y4[k].x * f0 + a.x * f1;
                o.y = y4[k].y * f0 + a.y * f1;
                o.z = y4[k].z * f0 + a.z * f1;
                o.w = y4[k].w * f0 + a.w * f1;
                dst[lane + 32 * k] = o;
            }
            if (lane == 0) {
                g_partm[(b * 32 + chunk) * 4 + h] = mm;
                g_partz[(b * 32 + chunk) * 4 + h] = Z * f0 + Z1 * f1;
            }
        }
    }
    gbar(3);

    // ======================= Phase D: combine =======================
    // 256 blocks: b = blk>>5; h = (blk&31)>>3; slice = blk&7 (128 channels)
    {
        float* red  = (float*)sraw;               // 8
        float* sm   = red + 8;                    // 32
        float* ez   = sm + 32;                    // 32
        float* coef = ez + 32;                    // 32
        float* s0p  = coef + 32;                  // 1
        float* sacc = s0p + 1;                    // 256

        int b = blk >> 5, h = (blk & 31) >> 3, slice = blk & 7;

        const float* wkh = g_wk + h * 1024;
        float pp = 0.f;
        #pragma unroll
        for (int k = 0; k < 4; ++k) pp += tmp[tid * 4 + k] * wkh[tid * 4 + k];
        #pragma unroll
        for (int d = 1; d < 32; d <<= 1) pp += __shfl_xor_sync(0xffffffffu, pp, d);
        if (lane == 0) red[warp] = pp;
        if (tid < 32) {
            sm[tid] = g_partm[(b * 32 + tid) * 4 + h];
            ez[tid] = g_partz[(b * 32 + tid) * 4 + h];
        }
        __syncthreads();
        if (tid == 0) {
            float s = 0.f;
            #pragma unroll
            for (int w = 0; w < 8; ++w) s += red[w];
            s0p[0] = s;
        }
        __syncthreads();
        float s0 = s0p[0];
        float M = s0;
        #pragma unroll
        for (int i = 0; i < 32; ++i) M = fmaxf(M, sm[i]);
        if (tid < 32) coef[tid] = __expf(sm[tid] - M);
        __syncthreads();
        float e0 = __expf(s0 - M);
        float Zt = e0;
        #pragma unroll
        for (int i = 0; i < 32; ++i) Zt += coef[i] * ez[i];
        float inv = 1.f / Zt;

        int cch = slice * 128 + (tid & 127);
        int hp  = tid >> 7;
        const float* base = g_party + (((size_t)b * 32 + hp * 16) * 4 + h) * 1024 + cch;
        const float* cf = coef + hp * 16;
        float acc = 0.f;
        #pragma unroll
        for (int i = 0; i < 16; i += 8) {
            float v0 = base[(size_t)(i + 0) * 4096];
            float v1 = base[(size_t)(i + 1) * 4096];
            float v2 = base[(size_t)(i + 2) * 4096];
            float v3 = base[(size_t)(i + 3) * 4096];
            float v4 = base[(size_t)(i + 4) * 4096];
            float v5 = base[(size_t)(i + 5) * 4096];
            float v6 = base[(size_t)(i + 6) * 4096];
            float v7 = base[(size_t)(i + 7) * 4096];
            acc += cf[i + 0] * v0 + cf[i + 1] * v1 + cf[i + 2] * v2 + cf[i + 3] * v3
                 + cf[i + 4] * v4 + cf[i + 5] * v5 + cf[i + 6] * v6 + cf[i + 7] * v7;
        }
        if (hp == 0) acc += e0 * tmp[cch];
        sacc[hp * 128 + (tid & 127)] = acc;
        __syncthreads();
        if (tid < 128)
            g_ybar[(size_t)(b * 4 + h) * 1024 + slice * 128 + tid] =
                (sacc[tid] + sacc[128 + tid]) * inv;
    }
    gbar(4);

    // ======================= Phase E: gemv1 partials =======================
    // 256 blocks: jblk = blk&3, cc = blk>>2 (16 c-rows)
    {
        float* ys = (float*)sraw;   // [8][16]
        int jblk = blk & 3, cc = blk >> 2;
        if (tid < 128) {
            int bb = tid >> 4, cr = tid & 15;
            ys[bb * 16 + cr] = g_ybar[(size_t)(bb * 4 + jblk) * 1024 + cc * 16 + cr];
        }
        __syncthreads();
        int j = jblk * 256 + tid;
        const float* Wcol = Wqkv + 2048 + j + (size_t)cc * 16 * 3072;
        float acc[8] = {0.f, 0.f, 0.f, 0.f, 0.f, 0.f, 0.f, 0.f};
        #pragma unroll
        for (int r0 = 0; r0 < 16; r0 += 8) {
            float w0 = Wcol[(size_t)(r0 + 0) * 3072];
            float w1 = Wcol[(size_t)(r0 + 1) * 3072];
            float w2 = Wcol[(size_t)(r0 + 2) * 3072];
            float w3 = Wcol[(size_t)(r0 + 3) * 3072];
            float w4 = Wcol[(size_t)(r0 + 4) * 3072];
            float w5 = Wcol[(size_t)(r0 + 5) * 3072];
            float w6 = Wcol[(size_t)(r0 + 6) * 3072];
            float w7 = Wcol[(size_t)(r0 + 7) * 3072];
            #pragma unroll
            for (int bb = 0; bb < 8; ++bb) {
                const float* yr = ys + bb * 16 + r0;
                acc[bb] += yr[0] * w0 + yr[1] * w1 + yr[2] * w2 + yr[3] * w3
                         + yr[4] * w4 + yr[5] * w5 + yr[6] * w6 + yr[7] * w7;
            }
        }
        #pragma unroll
        for (int bb = 0; bb < 8; ++bb)
            g_p1[(size_t)(cc * 8 + bb) * 1024 + j] = acc[bb];
    }
    gbar(5);

    // ======================= Phase F1: reduce p1 -> out0 =======================
    // blocks 0..31: b = blk>>2, quarter = blk&3
    if (blk < 32) {
        int b = blk >> 2, q = blk & 3;
        int j = q * 256 + tid;
        float s0 = 0.f, s1 = 0.f;
        for (int cc = 0; cc < 64; cc += 8) {
            float v0 = g_p1[(size_t)((cc + 0) * 8 + b) * 1024 + j];
            float v1 = g_p1[(size_t)((cc + 1) * 8 + b) * 1024 + j];
            float v2 = g_p1[(size_t)((cc + 2) * 8 + b) * 1024 + j];
            float v3 = g_p1[(size_t)((cc + 3) * 8 + b) * 1024 + j];
            float v4 = g_p1[(size_t)((cc + 4) * 8 + b) * 1024 + j];
            float v5 = g_p1[(size_t)((cc + 5) * 8 + b) * 1024 + j];
            float v6 = g_p1[(size_t)((cc + 6) * 8 + b) * 1024 + j];
            float v7 = g_p1[(size_t)((cc + 7) * 8 + b) * 1024 + j];
            s0 += (v0 + v1) + (v2 + v3);
            s1 += (v4 + v5) + (v6 + v7);
        }
        g_out0[b * 1024 + j] = bqkv[2048 + j] + s0 + s1;
    }
    gbar(6);

    // ======================= Phase G: gemv2 partials =======================
    // 256 blocks: jblk = blk&3, ic = blk>>2 (16 i-rows)
    {
        float* os = (float*)sraw;   // [8][16]
        int jblk = blk & 3, ic = blk >> 2;
        if (tid < 128) {
            int bb = tid >> 4, ir = tid & 15;
            os[bb * 16 + ir] = g_out0[bb * 1024 + ic * 16 + ir];
        }
        __syncthreads();
        int j = jblk * 256 + tid;
        const float* Wcol = Wv + j + (size_t)ic * 16 * 1024;
        float acc[8] = {0.f, 0.f, 0.f, 0.f, 0.f, 0.f, 0.f, 0.f};
        #pragma unroll
        for (int r0 = 0; r0 < 16; r0 += 8) {
            float w0 = Wcol[(size_t)(r0 + 0) * 1024];
            float w1 = Wcol[(size_t)(r0 + 1) * 1024];
            float w2 = Wcol[(size_t)(r0 + 2) * 1024];
            float w3 = Wcol[(size_t)(r0 + 3) * 1024];
            float w4 = Wcol[(size_t)(r0 + 4) * 1024];
            float w5 = Wcol[(size_t)(r0 + 5) * 1024];
            float w6 = Wcol[(size_t)(r0 + 6) * 1024];
            float w7 = Wcol[(size_t)(r0 + 7) * 1024];
            #pragma unroll
            for (int bb = 0; bb < 8; ++bb) {
                const float* orow = os + bb * 16 + r0;
                acc[bb] += orow[0] * w0 + orow[1] * w1 + orow[2] * w2 + orow[3] * w3
                         + orow[4] * w4 + orow[5] * w5 + orow[6] * w6 + orow[7] * w7;
            }
        }
        #pragma unroll
        for (int bb = 0; bb < 8; ++bb)
            g_p2[(size_t)(ic * 8 + bb) * 1024 + j] = acc[bb];
    }
    gbar(7);

    // ======================= Phase H: reduce p2 + bv -> out =======================
    // blocks 0..63: 128 outputs each, parts split across two thread-halves
    if (blk < 64) {
        float* sacc = (float*)sraw;   // [2][128]
        int idx = blk * 128 + (tid & 127);
        int b = idx >> 10, j = idx & 1023;
        int hp = tid >> 7;
        float s0 = 0.f, s1 = 0.f;
        int icbase = hp * 32;
        #pragma unroll
        for (int ic = 0; ic < 32; ic += 8) {
            float v0 = g_p2[(size_t)((icbase + ic + 0) * 8 + b) * 1024 + j];
            float v1 = g_p2[(size_t)((icbase + ic + 1) * 8 + b) * 1024 + j];
            float v2 = g_p2[(size_t)((icbase + ic + 2) * 8 + b) * 1024 + j];
            float v3 = g_p2[(size_t)((icbase + ic + 3) * 8 + b) * 1024 + j];
            float v4 = g_p2[(size_t)((icbase + ic + 4) * 8 + b) * 1024 + j];
            float v5 = g_p2[(size_t)((icbase + ic + 5) * 8 + b) * 1024 + j];
            float v6 = g_p2[(size_t)((icbase + ic + 6) * 8 + b) * 1024 + j];
            float v7 = g_p2[(size_t)((icbase + ic + 7) * 8 + b) * 1024 + j];
            s0 += (v0 + v1) + (v2 + v3);
            s1 += (v4 + v5) + (v6 + v7);
        }
        sacc[hp * 128 + (tid & 127)] = s0 + s1;
        __syncthreads();
        if (tid < 128) {
            int oidx = blk * 128 + tid;
            out[oidx] = bv[oidx & 1023] + sacc[tid] + sacc[128 + tid];
        }
    }

    // ======================= Final: arrive-only barrier + counter reset =======================
    __syncthreads();
    if (tid == 0) {
        __threadfence();
        atomicAdd(&g_bar[8], 1u);
    }
    if (blk == 0 && tid == 0) {
        volatile unsigned* p = &g_bar[8];
        while (*p < GR) { }
        #pragma unroll
        for (int i = 0; i < 16; ++i) g_bar[i] = 0;
        __threadfence();
    }
}

// ---------------------------------------------------------------------------
extern "C" void kernel_launch(void* const* d_in, const int* in_sizes, int n_in,
                              void* d_out, int out_size) {
    const float* x    = (const float*)d_in[0];
    const float* tmp  = (const float*)d_in[1];
    const float* Wqkv = (const float*)d_in[2];
    const float* bqkv = (const float*)d_in[3];
    const float* Wv   = (const float*)d_in[4];
    const float* bv   = (const float*)d_in[5];

    k_fused<<<GR, 256>>>(x, tmp, Wqkv, bqkv, Wv, bv, (float*)d_out);
}